// round 5
// baseline (speedup 1.0000x reference)
#include <cuda_runtime.h>
#include <cstdint>
#include <cstddef>

// ---------------------------------------------------------------------------
// NeuralODE Dopri5. GEMMs: mma.sync m16n8k8 TF32 (3xTF32 split), all operands
// pre-split in gmem (hi/lo), streamed via 4-stage cp.async pipeline, ldmatrix
// fragment loads. RK combine + re-split fused into layer-3 epilogue.
// ---------------------------------------------------------------------------

#define BB 1024
#define DD 256
#define HH 512
#define N_STEPS 40
#define HSTEP 0.25f

__device__ float g_y   [BB * DD];
__device__ float g_yhi [BB * DD], g_ylo [BB * DD];
__device__ float g_cmbhi[BB * DD], g_cmblo[BB * DD];
__device__ float g_k [6][BB * DD];
__device__ float g_h1hi[BB * HH], g_h1lo[BB * HH];
__device__ float g_h2hi[BB * HH], g_h2lo[BB * HH];
__device__ float g_W1hi[HH * DD], g_W1lo[HH * DD];
__device__ float g_W2hi[HH * HH], g_W2lo[HH * HH];
__device__ float g_W3hi[DD * HH], g_W3lo[DD * HH];

struct Epi {
    const float* yin;
    const float* ks[4];
    float        cks[4];
    int          nks;
    float        cself;
    float*       auxhi;
    float*       auxlo;
    float*       auxfp;
    float*       emit;
    int          t;
};

// ----------------------------- helpers -------------------------------------
__device__ __forceinline__ uint32_t smem_u32(const void* p) {
    uint32_t a;
    asm("{ .reg .u64 t; cvta.to.shared.u64 t, %1; cvt.u32.u64 %0, t; }"
        : "=r"(a) : "l"(p));
    return a;
}
__device__ __forceinline__ void tf32split(float x, uint32_t& hi, uint32_t& lo) {
    uint32_t h; asm("cvt.rna.tf32.f32 %0, %1;" : "=r"(h) : "f"(x));
    float r = x - __uint_as_float(h);
    asm("cvt.rna.tf32.f32 %0, %1;" : "=r"(lo) : "f"(r));
    hi = h;
}
__device__ __forceinline__ void cp16(uint32_t d, const float* s) {
    asm volatile("cp.async.cg.shared.global [%0], [%1], 16;"
                 :: "r"(d), "l"(s) : "memory");
}
__device__ __forceinline__ void cp_commit() {
    asm volatile("cp.async.commit_group;" ::: "memory");
}
__device__ __forceinline__ void cp_wait2() {
    asm volatile("cp.async.wait_group 2;" ::: "memory");
}
__device__ __forceinline__ void ldm4(uint32_t* r, uint32_t addr) {
    asm volatile("ldmatrix.sync.aligned.m8n8.x4.shared.b16 {%0,%1,%2,%3}, [%4];"
                 : "=r"(r[0]), "=r"(r[1]), "=r"(r[2]), "=r"(r[3]) : "r"(addr));
}
__device__ __forceinline__ void mma8(float* d, const uint32_t* a,
                                     uint32_t b0, uint32_t b1) {
    asm volatile(
        "mma.sync.aligned.m16n8k8.row.col.f32.tf32.tf32.f32 "
        "{%0,%1,%2,%3}, {%4,%5,%6,%7}, {%8,%9}, {%0,%1,%2,%3};"
        : "+f"(d[0]), "+f"(d[1]), "+f"(d[2]), "+f"(d[3])
        : "r"(a[0]), "r"(a[1]), "r"(a[2]), "r"(a[3]), "r"(b0), "r"(b1));
}

// ---------------------------------------------------------------------------
// GEMM: C[M,N] = act(A @ W^T + bias), A/W given pre-split as hi/lo tf32.
// 256 threads, warp grid 2(M)x4(N), warp tile (16*MT)x16, CTA tile (32*MT)x64.
// 4-stage cp.async pipeline, BK=32. Smem rows 128B, XOR swizzle
// col4 ^= 4*(row&7) -> conflict-free cp.async stores and ldmatrix gathers.
// Stage layout (bytes): Ahi[AB] Alo[AB] Whi[8192] Wlo[8192], AB = BM*128.
// MODE 0: relu, store split hi/lo. MODE 1: linear store fp32 + fused RK epi.
// ---------------------------------------------------------------------------
#define NS 4

template<int MT, int MODE>
__global__ __launch_bounds__(256, 1)
void gemm_tc(const float* __restrict__ Ahi, const float* __restrict__ Alo,
             const float* __restrict__ Whi, const float* __restrict__ Wlo,
             const float* __restrict__ bias,
             float* __restrict__ C, float* __restrict__ Clo,
             int K, int N, Epi ep)
{
    constexpr int BM = 32 * MT;
    constexpr uint32_t AB = BM * 128;          // bytes per A part per stage
    constexpr uint32_t WOFF = 2 * AB;          // Whi offset
    constexpr uint32_t STRIDE = 2 * AB + 16384;

    extern __shared__ float smem[];
    const uint32_t sb = smem_u32(smem);
    const int tid  = threadIdx.x;
    const int warp = tid >> 5, lane = tid & 31;
    const int wM = warp >> 2, wN = warp & 3;
    const int g = lane >> 2, c = lane & 3;
    const int m0 = blockIdx.y * BM, n0 = blockIdx.x * 64;

    // loader geometry: chunk idx -> (row, col4)
    const int lr  = tid >> 3;                  // 0..31
    const int lc4 = (tid & 7) * 4;
    const uint32_t ssc = ((uint32_t)lc4 ^ (((uint32_t)lr & 7) << 2)) * 4;
    const uint32_t sAd = (uint32_t)lr * 128 + ssc;

    // ldmatrix geometry
    const int quad = lane >> 3, l8 = lane & 7;
    const int arow = ((quad & 1) << 3) + l8;
    const uint32_t kcA = (uint32_t)((quad & 2) << 1);
    const int brow = ((quad & 2) << 2) + l8;
    const uint32_t kcB = (uint32_t)((quad & 1) << 2);

    uint32_t aoff[MT];
    #pragma unroll
    for (int i = 0; i < MT; i++)
        aoff[i] = (uint32_t)(wM * 16 * MT + i * 16 + arow) * 128;
    const uint32_t swzA = ((uint32_t)(arow & 7)) << 2;
    const uint32_t boff = WOFF + (uint32_t)(wN * 16 + brow) * 128;
    const uint32_t swzB = ((uint32_t)(brow & 7)) << 2;

    const int S = K >> 5;

    auto cpStage = [&](int s, int buf) {
        const int kk = s << 5;
        const uint32_t base = sb + (uint32_t)buf * STRIDE;
        // A: BM*8 chunks (MT per thread)
        #pragma unroll
        for (int q = 0; q < MT; q++) {
            const int row = lr + q * 32;
            const float* sa = Ahi + (size_t)(m0 + row) * K + kk + lc4;
            const float* sl = Alo + (size_t)(m0 + row) * K + kk + lc4;
            const uint32_t d = base + (uint32_t)q * 4096 + sAd;
            cp16(d,      sa);
            cp16(d + AB, sl);
        }
        // W: 512 chunks (2 per thread)
        #pragma unroll
        for (int q = 0; q < 2; q++) {
            const int row = lr + q * 32;
            const float* wh = Whi + (size_t)(n0 + row) * K + kk + lc4;
            const float* wl = Wlo + (size_t)(n0 + row) * K + kk + lc4;
            const uint32_t d = base + WOFF + (uint32_t)q * 4096 + sAd;
            cp16(d,        wh);
            cp16(d + 8192, wl);
        }
        cp_commit();
    };

    float acc[MT][2][4];
    #pragma unroll
    for (int i = 0; i < MT; i++)
        #pragma unroll
        for (int nt = 0; nt < 2; nt++)
            #pragma unroll
            for (int q = 0; q < 4; q++) acc[i][nt][q] = 0.0f;

    // prologue: stages 0..NS-2 in flight
    #pragma unroll
    for (int p = 0; p < NS - 1; p++) cpStage(p, p);
    cp_wait2();
    __syncthreads();

    for (int s = 0; s < S; s++) {
        const int nx = s + NS - 1;
        if (nx < S) cpStage(nx, nx & (NS - 1)); else cp_commit();

        const uint32_t base = sb + (uint32_t)(s & (NS - 1)) * STRIDE;
        #pragma unroll
        for (int j = 0; j < 4; j++) {
            const uint32_t colA = (((8u * j) | kcA) ^ swzA) * 4;
            const uint32_t colB = (((8u * j) | kcB) ^ swzB) * 4;
            uint32_t ah[MT][4], al[MT][4], bh[4], bl[4];
            #pragma unroll
            for (int i = 0; i < MT; i++) {
                ldm4(ah[i], base + aoff[i] + colA);
                ldm4(al[i], base + AB + aoff[i] + colA);
            }
            ldm4(bh, base + boff + colB);
            ldm4(bl, base + 8192 + boff + colB);
            #pragma unroll
            for (int nt = 0; nt < 2; nt++) {
                #pragma unroll
                for (int i = 0; i < MT; i++) {
                    mma8(acc[i][nt], ah[i], bh[2 * nt], bh[2 * nt + 1]);
                    mma8(acc[i][nt], ah[i], bl[2 * nt], bl[2 * nt + 1]);
                    mma8(acc[i][nt], al[i], bh[2 * nt], bh[2 * nt + 1]);
                }
            }
        }
        cp_wait2();
        __syncthreads();
    }

    // ---- epilogue ----
    #pragma unroll
    for (int i = 0; i < MT; i++) {
        #pragma unroll
        for (int nt = 0; nt < 2; nt++) {
            const int col  = n0 + wN * 16 + nt * 8 + 2 * c;
            const float b0v = bias[col], b1v = bias[col + 1];
            const int row0 = m0 + wM * 16 * MT + i * 16 + g;
            #pragma unroll
            for (int hh = 0; hh < 2; hh++) {
                const int row = row0 + 8 * hh;
                float v0 = acc[i][nt][2 * hh + 0] + b0v;
                float v1 = acc[i][nt][2 * hh + 1] + b1v;
                const size_t idx = (size_t)row * N + col;
                if (MODE == 0) {
                    v0 = fmaxf(v0, 0.0f); v1 = fmaxf(v1, 0.0f);
                    uint32_t h0, l0, h1, l1;
                    tf32split(v0, h0, l0); tf32split(v1, h1, l1);
                    *(float2*)(C   + idx) =
                        make_float2(__uint_as_float(h0), __uint_as_float(h1));
                    *(float2*)(Clo + idx) =
                        make_float2(__uint_as_float(l0), __uint_as_float(l1));
                } else {
                    *(float2*)(C + idx) = make_float2(v0, v1);
                    float a0 = ep.yin[idx]     + ep.cself * v0;
                    float a1 = ep.yin[idx + 1] + ep.cself * v1;
                    for (int t = 0; t < ep.nks; t++) {
                        a0 += ep.cks[t] * ep.ks[t][idx];
                        a1 += ep.cks[t] * ep.ks[t][idx + 1];
                    }
                    uint32_t h0, l0, h1, l1;
                    tf32split(a0, h0, l0); tf32split(a1, h1, l1);
                    *(float2*)(ep.auxhi + idx) =
                        make_float2(__uint_as_float(h0), __uint_as_float(h1));
                    *(float2*)(ep.auxlo + idx) =
                        make_float2(__uint_as_float(l0), __uint_as_float(l1));
                    if (ep.auxfp)
                        *(float2*)(ep.auxfp + idx) = make_float2(a0, a1);
                    if (ep.emit) {
                        const size_t o = (size_t)row * (10 * DD) + (size_t)ep.t * DD + col;
                        *(float2*)(ep.emit + o) = make_float2(a0, a1);
                    }
                }
            }
        }
    }
}

// Split X into tf32 hi/lo parts
__global__ void wsplit_kernel(const float* __restrict__ X,
                              float* __restrict__ hi, float* __restrict__ lo, int n)
{
    int i = blockIdx.x * blockDim.x + threadIdx.x;
    if (i < n) {
        uint32_t h, l;
        tf32split(X[i], h, l);
        hi[i] = __uint_as_float(h);
        lo[i] = __uint_as_float(l);
    }
}

extern "C" void kernel_launch(void* const* d_in, const int* in_sizes, int n_in,
                              void* d_out, int out_size)
{
    (void)in_sizes; (void)n_in; (void)out_size;
    const float* x0 = (const float*)d_in[0];
    // d_in[1] is T (int32, always 11) — baked into the graph.
    const float* W1 = (const float*)d_in[2];
    const float* b1 = (const float*)d_in[3];
    const float* W2 = (const float*)d_in[4];
    const float* b2 = (const float*)d_in[5];
    const float* W3 = (const float*)d_in[6];
    const float* b3 = (const float*)d_in[7];
    float* out = (float*)d_out;

    float *y, *yhi, *ylo, *cmbhi, *cmblo, *kbase;
    float *h1hi, *h1lo, *h2hi, *h2lo;
    float *w1h, *w1l, *w2h, *w2l, *w3h, *w3l;
    cudaGetSymbolAddress((void**)&y,     g_y);
    cudaGetSymbolAddress((void**)&yhi,   g_yhi);
    cudaGetSymbolAddress((void**)&ylo,   g_ylo);
    cudaGetSymbolAddress((void**)&cmbhi, g_cmbhi);
    cudaGetSymbolAddress((void**)&cmblo, g_cmblo);
    cudaGetSymbolAddress((void**)&kbase, g_k);
    cudaGetSymbolAddress((void**)&h1hi,  g_h1hi);
    cudaGetSymbolAddress((void**)&h1lo,  g_h1lo);
    cudaGetSymbolAddress((void**)&h2hi,  g_h2hi);
    cudaGetSymbolAddress((void**)&h2lo,  g_h2lo);
    cudaGetSymbolAddress((void**)&w1h,   g_W1hi);
    cudaGetSymbolAddress((void**)&w1l,   g_W1lo);
    cudaGetSymbolAddress((void**)&w2h,   g_W2hi);
    cudaGetSymbolAddress((void**)&w2l,   g_W2lo);
    cudaGetSymbolAddress((void**)&w3h,   g_W3hi);
    cudaGetSymbolAddress((void**)&w3l,   g_W3lo);
    float* k[6];
    for (int j = 0; j < 6; j++) k[j] = kbase + (size_t)j * BB * DD;

    const int SM2 = NS * (2 * 64 * 128 + 16384);   // MT=2: 131072
    const int SM1 = NS * (2 * 32 * 128 + 16384);   // MT=1: 98304
    cudaFuncSetAttribute(gemm_tc<2, 0>, cudaFuncAttributeMaxDynamicSharedMemorySize, SM2);
    cudaFuncSetAttribute(gemm_tc<1, 1>, cudaFuncAttributeMaxDynamicSharedMemorySize, SM1);

    // y = x0[:,0,:]; split into yhi/ylo
    cudaMemcpyAsync(y, x0, sizeof(float) * BB * DD, cudaMemcpyDeviceToDevice);
    wsplit_kernel<<<(BB * DD + 255) / 256, 256>>>(x0, yhi, ylo, BB * DD);
    wsplit_kernel<<<(HH * DD + 255) / 256, 256>>>(W1, w1h, w1l, HH * DD);
    wsplit_kernel<<<(HH * HH + 255) / 256, 256>>>(W2, w2h, w2l, HH * HH);
    wsplit_kernel<<<(DD * HH + 255) / 256, 256>>>(W3, w3h, w3l, DD * HH);

    // Dopri5 tableau
    const double A2[] = {1.0/5.0};
    const double A3[] = {3.0/40.0, 9.0/40.0};
    const double A4[] = {44.0/45.0, -56.0/15.0, 32.0/9.0};
    const double A5[] = {19372.0/6561.0, -25360.0/2187.0, 64448.0/6561.0, -212.0/729.0};
    const double A6[] = {9017.0/3168.0, -355.0/33.0, 46732.0/5247.0, 49.0/176.0, -5103.0/18656.0};
    const double* Arows[5] = {A2, A3, A4, A5, A6};

    const dim3 grd1(HH / 64, BB / 64);   // 128 CTAs
    const dim3 grd2(HH / 64, BB / 64);   // 128 CTAs
    const dim3 grd3(DD / 64, BB / 32);   // 128 CTAs

    Epi enone = {};

    for (int step = 0; step < N_STEPS; step++) {
        for (int s = 0; s < 6; s++) {
            const float* Ah = (s == 0) ? yhi : cmbhi;
            const float* Al = (s == 0) ? ylo : cmblo;
            gemm_tc<2, 0><<<grd1, 256, SM2>>>(Ah,   Al,   w1h, w1l, b1, h1hi, h1lo, DD, HH, enone);
            gemm_tc<2, 0><<<grd2, 256, SM2>>>(h1hi, h1lo, w2h, w2l, b2, h2hi, h2lo, HH, HH, enone);

            Epi ep = {};
            ep.yin = y;
            if (s < 5) {
                const double* row = Arows[s];
                ep.nks = s;
                for (int j = 0; j < s; j++) {
                    ep.ks[j]  = k[j];
                    ep.cks[j] = (float)((double)HSTEP * row[j]);
                }
                ep.cself = (float)((double)HSTEP * row[s]);
                ep.auxhi = cmbhi;
                ep.auxlo = cmblo;
                ep.auxfp = nullptr;
                ep.emit  = nullptr;
                ep.t     = 0;
            } else {
                ep.nks = 4;
                ep.ks[0] = k[0]; ep.cks[0] = (float)((double)HSTEP * (35.0 / 384.0));
                ep.ks[1] = k[2]; ep.cks[1] = (float)((double)HSTEP * (500.0 / 1113.0));
                ep.ks[2] = k[3]; ep.cks[2] = (float)((double)HSTEP * (125.0 / 192.0));
                ep.ks[3] = k[4]; ep.cks[3] = (float)((double)HSTEP * (-2187.0 / 6784.0));
                ep.cself = (float)((double)HSTEP * (11.0 / 84.0));
                ep.auxhi = yhi;
                ep.auxlo = ylo;
                ep.auxfp = y;
                ep.emit  = ((step & 3) == 3) ? out : nullptr;
                ep.t     = step >> 2;
            }
            gemm_tc<1, 1><<<grd3, 256, SM1>>>(h2hi, h2lo, w3h, w3l, b3, k[s], nullptr, HH, DD, ep);
        }
    }
}

// round 7
// speedup vs baseline: 1.3245x; 1.3245x over previous
#include <cuda_runtime.h>
#include <cstdint>
#include <cstddef>

// ---------------------------------------------------------------------------
// NeuralODE Dopri5. GEMMs: mma.sync m16n8k8 TF32, 3xTF32 split.
// A: LDG -> tf32split -> STS (fp32 activations in gmem). W: pre-split hi/lo,
// cp.async. Double-buffered BK=32 stages, ldmatrix fragments.
// 16 warps / CTA on 64x64 tiles (latency hiding), RK combine fused in L3 epi.
// ---------------------------------------------------------------------------

#define BB 1024
#define DD 256
#define HH 512
#define N_STEPS 40
#define HSTEP 0.25f

__device__ float g_y   [BB * DD];
__device__ float g_ycmb[BB * DD];
__device__ float g_k [6][BB * DD];
__device__ float g_h1[BB * HH];
__device__ float g_h2[BB * HH];
__device__ float g_W1hi[HH * DD], g_W1lo[HH * DD];
__device__ float g_W2hi[HH * HH], g_W2lo[HH * HH];
__device__ float g_W3hi[DD * HH], g_W3lo[DD * HH];

struct Epi {
    const float* yin;
    const float* ks[4];
    float        cks[4];
    int          nks;
    float        cself;
    float*       aux;
    float*       emit;
    int          t;
};

// ----------------------------- helpers -------------------------------------
__device__ __forceinline__ uint32_t smem_u32(const void* p) {
    uint32_t a;
    asm("{ .reg .u64 t; cvta.to.shared.u64 t, %1; cvt.u32.u64 %0, t; }"
        : "=r"(a) : "l"(p));
    return a;
}
__device__ __forceinline__ void tf32split(float x, uint32_t& hi, uint32_t& lo) {
    uint32_t h; asm("cvt.rna.tf32.f32 %0, %1;" : "=r"(h) : "f"(x));
    float r = x - __uint_as_float(h);
    asm("cvt.rna.tf32.f32 %0, %1;" : "=r"(lo) : "f"(r));
    hi = h;
}
__device__ __forceinline__ void sts128(uint32_t a, uint32_t x, uint32_t y,
                                       uint32_t z, uint32_t w) {
    asm volatile("st.shared.v4.b32 [%0], {%1,%2,%3,%4};"
                 :: "r"(a), "r"(x), "r"(y), "r"(z), "r"(w) : "memory");
}
__device__ __forceinline__ void cp16(uint32_t d, const float* s) {
    asm volatile("cp.async.cg.shared.global [%0], [%1], 16;"
                 :: "r"(d), "l"(s) : "memory");
}
__device__ __forceinline__ void ldm4(uint32_t* r, uint32_t addr) {
    asm volatile("ldmatrix.sync.aligned.m8n8.x4.shared.b16 {%0,%1,%2,%3}, [%4];"
                 : "=r"(r[0]), "=r"(r[1]), "=r"(r[2]), "=r"(r[3]) : "r"(addr));
}
__device__ __forceinline__ void mma8(float* d, const uint32_t* a,
                                     uint32_t b0, uint32_t b1) {
    asm volatile(
        "mma.sync.aligned.m16n8k8.row.col.f32.tf32.tf32.f32 "
        "{%0,%1,%2,%3}, {%4,%5,%6,%7}, {%8,%9}, {%0,%1,%2,%3};"
        : "+f"(d[0]), "+f"(d[1]), "+f"(d[2]), "+f"(d[3])
        : "r"(a[0]), "r"(a[1]), "r"(a[2]), "r"(a[3]), "r"(b0), "r"(b1));
}

// ---------------------------------------------------------------------------
// GEMM: C[M,N] = act(A @ W^T + bias). WM in {2,4}: warp grid WM(M) x 4(N),
// threads = WM*128, CTA tile (16*WM) x 64, warp tile 16x16. BK=32, double
// buffered. Smem rows 128B, XOR swizzle col4 ^= 4*(row&7): conflict-free
// STS.128, cp.async and ldmatrix.
// Stage layout (bytes): Ahi[AB] Alo[AB] Whi[8192] Wlo[8192], AB = 16*WM*128.
// MODE 0: relu fp32 store. MODE 1: linear store + fused RK-combine epilogue.
// ---------------------------------------------------------------------------
template<int WM, int MODE>
__global__ __launch_bounds__(WM * 128, 1)
void gemm_tc(const float* __restrict__ A,
             const float* __restrict__ Whi, const float* __restrict__ Wlo,
             const float* __restrict__ bias, float* __restrict__ C,
             int K, int N, Epi ep)
{
    constexpr int BM = 16 * WM;
    constexpr int NT = WM * 128;
    constexpr uint32_t AB = (uint32_t)BM * 128;
    constexpr uint32_t WOFF = 2 * AB;
    constexpr uint32_t STRIDE = 2 * AB + 16384;
    constexpr int WQ = 512 / NT;              // W chunks per thread (1 or 2)

    extern __shared__ float smem[];
    const uint32_t sb = smem_u32(smem);
    const int tid  = threadIdx.x;
    const int warp = tid >> 5, lane = tid & 31;
    const int wM = warp >> 2, wN = warp & 3;
    const int g = lane >> 2, c = lane & 3;
    const int m0 = blockIdx.y * BM, n0 = blockIdx.x * 64;

    // loader geometry
    const int lr  = tid >> 3;                 // 0 .. NT/8-1 (== BM-1)
    const int lc4 = (tid & 7) * 4;
    const uint32_t ssc = ((uint32_t)lc4 ^ (((uint32_t)lr & 7) << 2)) * 4;

    // ldmatrix geometry
    const int quad = lane >> 3, l8 = lane & 7;
    const int arow = ((quad & 1) << 3) + l8;
    const uint32_t kcA = (uint32_t)((quad & 2) << 1);
    const int brow = ((quad & 2) << 2) + l8;
    const uint32_t kcB = (uint32_t)((quad & 1) << 2);

    const uint32_t aoff = (uint32_t)(wM * 16 + arow) * 128;
    const uint32_t swzA = ((uint32_t)(arow & 7)) << 2;
    const uint32_t boff = WOFF + (uint32_t)(wN * 16 + brow) * 128;
    const uint32_t swzB = ((uint32_t)(brow & 7)) << 2;

    const int S = K >> 5;
    float4 pa;

    auto ldA = [&](int s) {
        pa = *(const float4*)(A + (size_t)(m0 + lr) * K + (s << 5) + lc4);
    };
    auto cpW = [&](int s, int b) {
        const uint32_t d0 = sb + (uint32_t)b * STRIDE + WOFF;
        #pragma unroll
        for (int q = 0; q < WQ; q++) {
            const int row = lr + q * (NT / 8);
            const float* wh = Whi + (size_t)(n0 + row) * K + (s << 5) + lc4;
            const float* wl = Wlo + (size_t)(n0 + row) * K + (s << 5) + lc4;
            const uint32_t d = d0 + (uint32_t)row * 128 + ssc;
            cp16(d,        wh);
            cp16(d + 8192, wl);
        }
        asm volatile("cp.async.commit_group;" ::: "memory");
    };
    auto stA = [&](int b) {
        const uint32_t d = sb + (uint32_t)b * STRIDE + (uint32_t)lr * 128 + ssc;
        uint32_t hx, hy, hz, hw, lx, ly, lz, lw;
        tf32split(pa.x, hx, lx); tf32split(pa.y, hy, ly);
        tf32split(pa.z, hz, lz); tf32split(pa.w, hw, lw);
        sts128(d,      hx, hy, hz, hw);
        sts128(d + AB, lx, ly, lz, lw);
    };

    float acc[2][4];
    #pragma unroll
    for (int nt = 0; nt < 2; nt++)
        #pragma unroll
        for (int q = 0; q < 4; q++) acc[nt][q] = 0.0f;

    ldA(0);
    cpW(0, 0);

    for (int s = 0; s < S; s++) {
        const int b = s & 1;
        stA(b);
        asm volatile("cp.async.wait_group 0;" ::: "memory");
        __syncthreads();
        if (s + 1 < S) { ldA(s + 1); cpW(s + 1, b ^ 1); }

        const uint32_t base = sb + (uint32_t)b * STRIDE;
        #pragma unroll
        for (int j = 0; j < 4; j++) {
            const uint32_t colA = (((8u * j) | kcA) ^ swzA) * 4;
            const uint32_t colB = (((8u * j) | kcB) ^ swzB) * 4;
            uint32_t ah[4], al[4], bh[4], bl[4];
            ldm4(ah, base + aoff + colA);
            ldm4(al, base + AB + aoff + colA);
            ldm4(bh, base + boff + colB);
            ldm4(bl, base + 8192 + boff + colB);
            // product-type-major order: independent chains interleave
            mma8(acc[0], ah, bh[0], bh[1]);
            mma8(acc[1], ah, bh[2], bh[3]);
            mma8(acc[0], ah, bl[0], bl[1]);
            mma8(acc[1], ah, bl[2], bl[3]);
            mma8(acc[0], al, bh[0], bh[1]);
            mma8(acc[1], al, bh[2], bh[3]);
        }
        __syncthreads();
    }

    // ---- epilogue ----
    #pragma unroll
    for (int nt = 0; nt < 2; nt++) {
        const int col  = n0 + wN * 16 + nt * 8 + 2 * c;
        const float b0v = bias[col], b1v = bias[col + 1];
        const int row0 = m0 + wM * 16 + g;
        #pragma unroll
        for (int hh = 0; hh < 2; hh++) {
            const int row = row0 + 8 * hh;
            float v0 = acc[nt][2 * hh + 0] + b0v;
            float v1 = acc[nt][2 * hh + 1] + b1v;
            const size_t idx = (size_t)row * N + col;
            if (MODE == 0) {
                v0 = fmaxf(v0, 0.0f); v1 = fmaxf(v1, 0.0f);
                *(float2*)(C + idx) = make_float2(v0, v1);
            } else {
                *(float2*)(C + idx) = make_float2(v0, v1);
                float a0 = ep.yin[idx]     + ep.cself * v0;
                float a1 = ep.yin[idx + 1] + ep.cself * v1;
                for (int t = 0; t < ep.nks; t++) {
                    a0 += ep.cks[t] * ep.ks[t][idx];
                    a1 += ep.cks[t] * ep.ks[t][idx + 1];
                }
                *(float2*)(ep.aux + idx) = make_float2(a0, a1);
                if (ep.emit) {
                    const size_t o = (size_t)row * (10 * DD) + (size_t)ep.t * DD + col;
                    *(float2*)(ep.emit + o) = make_float2(a0, a1);
                }
            }
        }
    }
}

// Split W into tf32 hi/lo parts
__global__ void wsplit_kernel(const float* __restrict__ W,
                              float* __restrict__ hi, float* __restrict__ lo, int n)
{
    int i = blockIdx.x * blockDim.x + threadIdx.x;
    if (i < n) {
        uint32_t h, l;
        tf32split(W[i], h, l);
        hi[i] = __uint_as_float(h);
        lo[i] = __uint_as_float(l);
    }
}

extern "C" void kernel_launch(void* const* d_in, const int* in_sizes, int n_in,
                              void* d_out, int out_size)
{
    (void)in_sizes; (void)n_in; (void)out_size;
    const float* x0 = (const float*)d_in[0];
    // d_in[1] is T (int32, always 11) — baked into the graph.
    const float* W1 = (const float*)d_in[2];
    const float* b1 = (const float*)d_in[3];
    const float* W2 = (const float*)d_in[4];
    const float* b2 = (const float*)d_in[5];
    const float* W3 = (const float*)d_in[6];
    const float* b3 = (const float*)d_in[7];
    float* out = (float*)d_out;

    float *y, *ycmb, *h1, *h2, *kbase;
    float *w1h, *w1l, *w2h, *w2l, *w3h, *w3l;
    cudaGetSymbolAddress((void**)&y,     g_y);
    cudaGetSymbolAddress((void**)&ycmb,  g_ycmb);
    cudaGetSymbolAddress((void**)&h1,    g_h1);
    cudaGetSymbolAddress((void**)&h2,    g_h2);
    cudaGetSymbolAddress((void**)&kbase, g_k);
    cudaGetSymbolAddress((void**)&w1h,   g_W1hi);
    cudaGetSymbolAddress((void**)&w1l,   g_W1lo);
    cudaGetSymbolAddress((void**)&w2h,   g_W2hi);
    cudaGetSymbolAddress((void**)&w2l,   g_W2lo);
    cudaGetSymbolAddress((void**)&w3h,   g_W3hi);
    cudaGetSymbolAddress((void**)&w3l,   g_W3lo);
    float* k[6];
    for (int j = 0; j < 6; j++) k[j] = kbase + (size_t)j * BB * DD;

    const int SM4 = 2 * (2 * 64 * 128 + 16384);   // WM=4: 65536
    const int SM2 = 2 * (2 * 32 * 128 + 16384);   // WM=2: 49152
    cudaFuncSetAttribute(gemm_tc<4, 0>, cudaFuncAttributeMaxDynamicSharedMemorySize, SM4);
    cudaFuncSetAttribute(gemm_tc<2, 1>, cudaFuncAttributeMaxDynamicSharedMemorySize, SM2);

    // y = x0[:,0,:]
    cudaMemcpyAsync(y, x0, sizeof(float) * BB * DD, cudaMemcpyDeviceToDevice);

    wsplit_kernel<<<(HH * DD + 255) / 256, 256>>>(W1, w1h, w1l, HH * DD);
    wsplit_kernel<<<(HH * HH + 255) / 256, 256>>>(W2, w2h, w2l, HH * HH);
    wsplit_kernel<<<(DD * HH + 255) / 256, 256>>>(W3, w3h, w3l, DD * HH);

    // Dopri5 tableau
    const double A2[] = {1.0/5.0};
    const double A3[] = {3.0/40.0, 9.0/40.0};
    const double A4[] = {44.0/45.0, -56.0/15.0, 32.0/9.0};
    const double A5[] = {19372.0/6561.0, -25360.0/2187.0, 64448.0/6561.0, -212.0/729.0};
    const double A6[] = {9017.0/3168.0, -355.0/33.0, 46732.0/5247.0, 49.0/176.0, -5103.0/18656.0};
    const double* Arows[5] = {A2, A3, A4, A5, A6};

    const dim3 grd1(HH / 64, BB / 64);   // 8 x 16 = 128 CTAs (512 thr)
    const dim3 grd2(HH / 64, BB / 64);   // 128 CTAs (512 thr)
    const dim3 grd3(DD / 64, BB / 32);   // 4 x 32 = 128 CTAs (256 thr)

    Epi enone = {};

    for (int step = 0; step < N_STEPS; step++) {
        for (int s = 0; s < 6; s++) {
            const float* Ain = (s == 0) ? y : ycmb;
            gemm_tc<4, 0><<<grd1, 512, SM4>>>(Ain, w1h, w1l, b1, h1, DD, HH, enone);
            gemm_tc<4, 0><<<grd2, 512, SM4>>>(h1,  w2h, w2l, b2, h2, HH, HH, enone);

            Epi ep = {};
            ep.yin = y;
            if (s < 5) {
                const double* row = Arows[s];
                ep.nks = s;
                for (int j = 0; j < s; j++) {
                    ep.ks[j]  = k[j];
                    ep.cks[j] = (float)((double)HSTEP * row[j]);
                }
                ep.cself = (float)((double)HSTEP * row[s]);
                ep.aux   = ycmb;
                ep.emit  = nullptr;
                ep.t     = 0;
            } else {
                ep.nks = 4;
                ep.ks[0] = k[0]; ep.cks[0] = (float)((double)HSTEP * (35.0 / 384.0));
                ep.ks[1] = k[2]; ep.cks[1] = (float)((double)HSTEP * (500.0 / 1113.0));
                ep.ks[2] = k[3]; ep.cks[2] = (float)((double)HSTEP * (125.0 / 192.0));
                ep.ks[3] = k[4]; ep.cks[3] = (float)((double)HSTEP * (-2187.0 / 6784.0));
                ep.cself = (float)((double)HSTEP * (11.0 / 84.0));
                ep.aux   = y;
                ep.emit  = ((step & 3) == 3) ? out : nullptr;
                ep.t     = step >> 2;
            }
            gemm_tc<2, 1><<<grd3, 256, SM2>>>(h2, w3h, w3l, b3, k[s], HH, DD, ep);
        }
    }
}